// round 6
// baseline (speedup 1.0000x reference)
#include <cuda_runtime.h>
#include <math.h>
#include <stdint.h>

#define B_   512
#define T_   128
#define DIN  256
#define U_   512
#define NPRE 1536    // [z | r | h] precomputed input projections
#define HS_STRIDE 520

// Scratch (static device arrays — allocation-free rule)
__device__ float g_pre[(size_t)T_ * B_ * NPRE];  // [t][b][1536]
__device__ float g_h  [(size_t)T_ * B_ * U_];    // [t][b][512]
__device__ float g_wt [(size_t)1536 * 512];      // WT[c][k]: rows 0-511 Wzh, 512-1023 Wrh, 1024-1535 Whh

typedef unsigned long long ull;

__device__ __forceinline__ ull dup2(float v) {
    ull r; asm("mov.b64 %0, {%1, %1};" : "=l"(r) : "f"(v)); return r;
}
__device__ __forceinline__ void fma2(ull& d, ull a, ull b) {
    asm("fma.rn.f32x2 %0, %1, %2, %0;" : "+l"(d) : "l"(a), "l"(b));
}
__device__ __forceinline__ float2 unpk(ull v) {
    float2 f; asm("mov.b64 {%0, %1}, %2;" : "=f"(f.x), "=f"(f.y) : "l"(v)); return f;
}
__device__ __forceinline__ float sigf(float x) {
    return 1.0f / (1.0f + expf(-x));
}
__device__ __forceinline__ uint32_t smem_u32(const void* p) {
    uint32_t a;
    asm("{ .reg .u64 t; cvta.to.shared.u64 t, %1; cvt.u32.u64 %0, t; }" : "=r"(a) : "l"(p));
    return a;
}
__device__ __forceinline__ uint32_t mapa32(uint32_t a, uint32_t r) {
    uint32_t o;
    asm("mapa.shared::cluster.u32 %0, %1, %2;" : "=r"(o) : "r"(a), "r"(r));
    return o;
}
__device__ __forceinline__ void st_rem1(uint32_t addr, float v) {
    asm volatile("st.shared::cluster.f32 [%0], %1;" :: "r"(addr), "f"(v) : "memory");
}
__device__ __forceinline__ void cluster_sync() {
    asm volatile("barrier.cluster.arrive.aligned;" ::: "memory");
    asm volatile("barrier.cluster.wait.aligned;" ::: "memory");
}

// ============================================================================
// Phase 0: transpose [Wzh|Wrh|Whh] (each [512,512] row-major, k-major rows)
// into WT[1536][512] where WT[c][k] = W[k][c]  (k contiguous per output col).
// grid (16, 48): blockIdx.x tiles k, blockIdx.y tiles c. 32x32 tiles.
// ============================================================================
__global__ void __launch_bounds__(256) k_tr(
    const float* __restrict__ Wzh, const float* __restrict__ Wrh,
    const float* __restrict__ Whh, float* __restrict__ WT)
{
    __shared__ float s[32][33];
    const int k0 = blockIdx.x * 32, c0 = blockIdx.y * 32;
    const int tx = threadIdx.x & 31, ty = threadIdx.x >> 5;   // 32 x 8
    const float* W = c0 < 512 ? Wzh : (c0 < 1024 ? Wrh : Whh);
    const int cc = c0 & 511;
    #pragma unroll
    for (int i = 0; i < 4; i++)
        s[ty + i * 8][tx] = W[(size_t)(k0 + ty + i * 8) * 512 + cc + tx];
    __syncthreads();
    #pragma unroll
    for (int i = 0; i < 4; i++)
        WT[(size_t)(c0 + ty + i * 8) * 512 + k0 + tx] = s[tx][ty + i * 8];
}

// ============================================================================
// Phase 1: pre[t][b][0:1536] = x[b][t][:] @ [Wzx | Wrx | Whx]
// M=65536 (m = b*128 + t), N=1536, K=256. 128x128 tiles, BK=8, 8x8/thread,
// f32x2, double-buffered global loads.
// ============================================================================
__global__ void __launch_bounds__(256) k_pre(
    const float* __restrict__ X,
    const float* __restrict__ Wzx, const float* __restrict__ Wrx, const float* __restrict__ Whx,
    float* __restrict__ pre)
{
    __shared__ __align__(16) float As[8][128];   // [k][m] transposed
    __shared__ __align__(16) float Bs[8][128];   // [k][n]

    const int tid = threadIdx.x;
    const int bm = blockIdx.x, bn = blockIdx.y;
    const int gate = (bn * 128) >> 9;
    const float* Wg = gate == 0 ? Wzx : (gate == 1 ? Wrx : Whx);
    const int ncol0 = bn * 128 - gate * 512;

    const int tx = tid & 15, ty = tid >> 4;
    const int m0 = ty * 8, n0 = tx * 8;

    const int arow = tid >> 1, acol = (tid & 1) * 4;
    const int brow = tid >> 5, bcol = (tid & 31) * 4;
    const float* Ap = X  + (size_t)(bm * 128 + arow) * DIN + acol;
    const float* Bp = Wg + (size_t)brow * U_ + ncol0 + bcol;

    ull acc[8][4];
    #pragma unroll
    for (int j = 0; j < 8; j++)
        #pragma unroll
        for (int p = 0; p < 4; p++) acc[j][p] = 0ull;

    float4 av = *(const float4*)(Ap);
    float4 bv = *(const float4*)(Bp);

    for (int k0 = 0; k0 < DIN; k0 += 8) {
        As[acol + 0][arow] = av.x; As[acol + 1][arow] = av.y;
        As[acol + 2][arow] = av.z; As[acol + 3][arow] = av.w;
        *(float4*)&Bs[brow][bcol] = bv;
        __syncthreads();
        if (k0 + 8 < DIN) {
            av = *(const float4*)(Ap + k0 + 8);
            bv = *(const float4*)(Bp + (size_t)(k0 + 8) * U_);
        }
        #pragma unroll
        for (int kk = 0; kk < 8; kk++) {
            ulonglong2 a01 = *(const ulonglong2*)&As[kk][m0];
            ulonglong2 a23 = *(const ulonglong2*)&As[kk][m0 + 4];
            ull ap[4] = {a01.x, a01.y, a23.x, a23.y};
            float4 b0 = *(const float4*)&Bs[kk][n0];
            float4 b1 = *(const float4*)&Bs[kk][n0 + 4];
            ull bd[8] = {dup2(b0.x), dup2(b0.y), dup2(b0.z), dup2(b0.w),
                         dup2(b1.x), dup2(b1.y), dup2(b1.z), dup2(b1.w)};
            #pragma unroll
            for (int j = 0; j < 8; j++)
                #pragma unroll
                for (int p = 0; p < 4; p++) fma2(acc[j][p], bd[j], ap[p]);
        }
        __syncthreads();
    }

    const int gn0 = bn * 128 + n0;
    #pragma unroll
    for (int m = 0; m < 8; m++) {
        int gm = bm * 128 + m0 + m;
        int b = gm >> 7, t = gm & 127;            // X row m = b*T + t
        float* dst = pre + (size_t)(t * B_ + b) * NPRE + gn0;
        float v[8];
        #pragma unroll
        for (int j = 0; j < 8; j++) { float2 f = unpk(acc[j][m >> 1]); v[j] = (m & 1) ? f.y : f.x; }
        *(float4*)(dst)     = make_float4(v[0], v[1], v[2], v[3]);
        *(float4*)(dst + 4) = make_float4(v[4], v[5], v[6], v[7]);
    }
}

// ============================================================================
// Phase 2: recurrence. 32 clusters x 4 CTAs. Cluster owns 16 batch rows;
// rank j owns cols [j*128,(j+1)*128) of z, r and h.
// hsT/rhsT are row-major per batch row (k contiguous) -> GEMMs accumulate
// f32x2 over k-pairs; weights from WT are k-contiguous LDG.128, double-buffered.
// DSMEM scalar stores broadcast r*h and h slices to the 3 peer CTAs.
// ============================================================================
__global__ void __launch_bounds__(256) __cluster_dims__(4, 1, 1) k_rec(
    const float* __restrict__ pre, const float* __restrict__ WT,
    const float* __restrict__ bz, const float* __restrict__ br, const float* __restrict__ bh,
    float* __restrict__ hall)
{
    extern __shared__ __align__(16) float smf[];
    float* hsT  = smf;                    // [16][520]  h,   row-major per batch row
    float* rhsT = smf + 16 * HS_STRIDE;   // [16][520]  r*h
    float* zsm  = smf + 32 * HS_STRIDE;   // [16][128]  z (local cols)

    const int tid  = threadIdx.x;
    const int rank = blockIdx.x & 3;
    const int cid  = blockIdx.x >> 2;
    const int b0   = cid * 16;
    const int jbase = rank * 128;

    const uint32_t sb = smem_u32(smf);
    uint32_t peer_hs[3], peer_rhs[3];
    #pragma unroll
    for (int d = 0; d < 3; d++) {
        const uint32_t pr = (rank + d + 1) & 3;
        peer_hs[d]  = mapa32(sb, pr);
        peer_rhs[d] = mapa32(sb + 16 * HS_STRIDE * 4, pr);
    }

    // zr mapping: thread = one of 256 zr columns (128 z + 128 r), all 16 rows
    const int zc  = tid & 127;
    const int isr = tid >> 7;
    const float* wp_zr = WT + (size_t)(isr * 512 + jbase + zc) * 512;
    const int precol = isr * 512 + jbase + zc;
    const float bzr = (isr ? br : bz)[jbase + zc];

    // h mapping: thread = one of 128 h columns x half the rows
    const int hc = tid & 127, mh = tid >> 7, m0 = mh * 8;
    const int k0h = jbase + hc;
    const float* wp_h = WT + (size_t)(1024 + k0h) * 512;
    const float bhc = bh[k0h];

    for (int i = tid; i < 16 * HS_STRIDE; i += 256) hsT[i] = 0.0f;
    cluster_sync();

    for (int t = 0; t < T_; t++) {
        const float* pre_t = pre + (size_t)(t * B_ + b0) * NPRE;

        float pz[16];
        #pragma unroll
        for (int m = 0; m < 16; m++) pz[m] = pre_t[(size_t)m * NPRE + precol];

        // ---------------- zr GEMM: 1 col x 16 rows, K=512, f32x2 over k ----
        ull acc[16];
        #pragma unroll
        for (int m = 0; m < 16; m++) acc[m] = 0ull;
        {
            ulonglong2 wa0 = *(const ulonglong2*)(wp_zr);
            ulonglong2 wa1 = *(const ulonglong2*)(wp_zr + 4);
            for (int kb = 0; kb < 512; kb += 16) {
                ulonglong2 wb0 = *(const ulonglong2*)(wp_zr + kb + 8);
                ulonglong2 wb1 = *(const ulonglong2*)(wp_zr + kb + 12);
                #pragma unroll
                for (int m = 0; m < 16; m++) {
                    const float* hp = hsT + m * HS_STRIDE + kb;
                    ulonglong2 h0 = *(const ulonglong2*)hp;
                    ulonglong2 h1 = *(const ulonglong2*)(hp + 4);
                    fma2(acc[m], wa0.x, h0.x); fma2(acc[m], wa0.y, h0.y);
                    fma2(acc[m], wa1.x, h1.x); fma2(acc[m], wa1.y, h1.y);
                }
                if (kb + 16 < 512) {
                    wa0 = *(const ulonglong2*)(wp_zr + kb + 16);
                    wa1 = *(const ulonglong2*)(wp_zr + kb + 20);
                }
                #pragma unroll
                for (int m = 0; m < 16; m++) {
                    const float* hp = hsT + m * HS_STRIDE + kb + 8;
                    ulonglong2 h0 = *(const ulonglong2*)hp;
                    ulonglong2 h1 = *(const ulonglong2*)(hp + 4);
                    fma2(acc[m], wb0.x, h0.x); fma2(acc[m], wb0.y, h0.y);
                    fma2(acc[m], wb1.x, h1.x); fma2(acc[m], wb1.y, h1.y);
                }
            }
        }

        // ---------------- z / r elementwise ----------------
        float vv[16];
        #pragma unroll
        for (int m = 0; m < 16; m++) {
            float2 f = unpk(acc[m]);
            vv[m] = sigf(f.x + f.y + pz[m] + bzr);
        }
        if (!isr) {
            #pragma unroll
            for (int m = 0; m < 16; m++) zsm[m * 128 + zc] = vv[m];
        } else {
            const int k0 = jbase + zc;
            #pragma unroll
            for (int m = 0; m < 16; m++) {
                float rh = vv[m] * hsT[m * HS_STRIDE + k0];
                rhsT[m * HS_STRIDE + k0] = rh;
                const uint32_t off = (uint32_t)(m * HS_STRIDE + k0) * 4;
                st_rem1(peer_rhs[0] + off, rh);
                st_rem1(peer_rhs[1] + off, rh);
                st_rem1(peer_rhs[2] + off, rh);
            }
        }
        cluster_sync();   // rhsT complete everywhere; zsm complete locally

        float phh[8];
        #pragma unroll
        for (int m = 0; m < 8; m++)
            phh[m] = pre_t[(size_t)(m0 + m) * NPRE + 1024 + k0h];

        // ---------------- h GEMM: 1 col x 8 rows, K=512, f32x2 over k -------
        ull acch[8];
        #pragma unroll
        for (int m = 0; m < 8; m++) acch[m] = 0ull;
        {
            ulonglong2 wa0 = *(const ulonglong2*)(wp_h);
            ulonglong2 wa1 = *(const ulonglong2*)(wp_h + 4);
            for (int kb = 0; kb < 512; kb += 16) {
                ulonglong2 wb0 = *(const ulonglong2*)(wp_h + kb + 8);
                ulonglong2 wb1 = *(const ulonglong2*)(wp_h + kb + 12);
                #pragma unroll
                for (int m = 0; m < 8; m++) {
                    const float* rp = rhsT + (m0 + m) * HS_STRIDE + kb;
                    ulonglong2 r0 = *(const ulonglong2*)rp;
                    ulonglong2 r1 = *(const ulonglong2*)(rp + 4);
                    fma2(acch[m], wa0.x, r0.x); fma2(acch[m], wa0.y, r0.y);
                    fma2(acch[m], wa1.x, r1.x); fma2(acch[m], wa1.y, r1.y);
                }
                if (kb + 16 < 512) {
                    wa0 = *(const ulonglong2*)(wp_h + kb + 16);
                    wa1 = *(const ulonglong2*)(wp_h + kb + 20);
                }
                #pragma unroll
                for (int m = 0; m < 8; m++) {
                    const float* rp = rhsT + (m0 + m) * HS_STRIDE + kb + 8;
                    ulonglong2 r0 = *(const ulonglong2*)rp;
                    ulonglong2 r1 = *(const ulonglong2*)(rp + 4);
                    fma2(acch[m], wb0.x, r0.x); fma2(acch[m], wb0.y, r0.y);
                    fma2(acch[m], wb1.x, r1.x); fma2(acch[m], wb1.y, r1.y);
                }
            }
        }

        // ---------------- h elementwise + writeback ----------------
        #pragma unroll
        for (int m = 0; m < 8; m++) {
            float2 f = unpk(acch[m]);
            float hcand = tanhf(f.x + f.y + phh[m] + bhc);
            float hold  = hsT[(m0 + m) * HS_STRIDE + k0h];
            float z     = zsm[(m0 + m) * 128 + hc];
            float hn = hold + z * (hcand - hold);
            hsT[(m0 + m) * HS_STRIDE + k0h] = hn;
            const uint32_t off = (uint32_t)((m0 + m) * HS_STRIDE + k0h) * 4;
            st_rem1(peer_hs[0] + off, hn);
            st_rem1(peer_hs[1] + off, hn);
            st_rem1(peer_hs[2] + off, hn);
            hall[(size_t)(t * B_ + b0 + m0 + m) * U_ + k0h] = hn;
        }
        cluster_sync();   // hsT updated everywhere for next step
    }
}

// ============================================================================
// Phase 3: out[b][t][:] = g_h[t][b][:] @ W_o + b_o
// M=65536 (m' = t*512 + b), N=512, K=512. Double-buffered.
// ============================================================================
__global__ void __launch_bounds__(256) k_out(
    const float* __restrict__ H, const float* __restrict__ Wo, const float* __restrict__ bo,
    float* __restrict__ out)
{
    __shared__ __align__(16) float As[8][128];
    __shared__ __align__(16) float Bs[8][128];

    const int tid = threadIdx.x;
    const int bm = blockIdx.x, bn = blockIdx.y;

    const int tx = tid & 15, ty = tid >> 4;
    const int m0 = ty * 8, n0 = tx * 8;

    const int arow = tid >> 1, acol = (tid & 1) * 4;
    const int brow = tid >> 5, bcol = (tid & 31) * 4;
    const float* Ap = H  + (size_t)(bm * 128 + arow) * U_ + acol;
    const float* Bp = Wo + (size_t)brow * U_ + bn * 128 + bcol;

    ull acc[8][4];
    #pragma unroll
    for (int j = 0; j < 8; j++)
        #pragma unroll
        for (int p = 0; p < 4; p++) acc[j][p] = 0ull;

    float4 av = *(const float4*)(Ap);
    float4 bv = *(const float4*)(Bp);

    for (int k0 = 0; k0 < U_; k0 += 8) {
        As[acol + 0][arow] = av.x; As[acol + 1][arow] = av.y;
        As[acol + 2][arow] = av.z; As[acol + 3][arow] = av.w;
        *(float4*)&Bs[brow][bcol] = bv;
        __syncthreads();
        if (k0 + 8 < U_) {
            av = *(const float4*)(Ap + k0 + 8);
            bv = *(const float4*)(Bp + (size_t)(k0 + 8) * U_);
        }
        #pragma unroll
        for (int kk = 0; kk < 8; kk++) {
            ulonglong2 a01 = *(const ulonglong2*)&As[kk][m0];
            ulonglong2 a23 = *(const ulonglong2*)&As[kk][m0 + 4];
            ull ap[4] = {a01.x, a01.y, a23.x, a23.y};
            float4 b0 = *(const float4*)&Bs[kk][n0];
            float4 b1 = *(const float4*)&Bs[kk][n0 + 4];
            ull bd[8] = {dup2(b0.x), dup2(b0.y), dup2(b0.z), dup2(b0.w),
                         dup2(b1.x), dup2(b1.y), dup2(b1.z), dup2(b1.w)};
            #pragma unroll
            for (int j = 0; j < 8; j++)
                #pragma unroll
                for (int p = 0; p < 4; p++) fma2(acc[j][p], bd[j], ap[p]);
        }
        __syncthreads();
    }

    const int gn0 = bn * 128 + n0;
    const float4 bo0 = *(const float4*)(bo + gn0);
    const float4 bo1 = *(const float4*)(bo + gn0 + 4);
    #pragma unroll
    for (int m = 0; m < 8; m++) {
        int mm = bm * 128 + m0 + m;            // h_all row = t*512 + b
        int b = mm & 511, t = mm >> 9;
        float* dst = out + (size_t)(b * T_ + t) * U_ + gn0;
        float v[8];
        #pragma unroll
        for (int j = 0; j < 8; j++) { float2 f = unpk(acc[j][m >> 1]); v[j] = (m & 1) ? f.y : f.x; }
        *(float4*)(dst)     = make_float4(v[0] + bo0.x, v[1] + bo0.y, v[2] + bo0.z, v[3] + bo0.w);
        *(float4*)(dst + 4) = make_float4(v[4] + bo1.x, v[5] + bo1.y, v[6] + bo1.z, v[7] + bo1.w);
    }
}

// ============================================================================
extern "C" void kernel_launch(void* const* d_in, const int* in_sizes, int n_in,
                              void* d_out, int out_size)
{
    const float* x    = (const float*)d_in[0];
    const float* Wzx  = (const float*)d_in[1];
    const float* Wrx  = (const float*)d_in[2];
    const float* Whx  = (const float*)d_in[3];
    const float* Wzh  = (const float*)d_in[4];
    const float* Wrh  = (const float*)d_in[5];
    const float* Whh  = (const float*)d_in[6];
    const float* bz   = (const float*)d_in[7];
    const float* br   = (const float*)d_in[8];
    const float* bh   = (const float*)d_in[9];
    // d_in[10..12] = W_q, W_k, W_v : dead code in the reference (attn unused)
    const float* Wo   = (const float*)d_in[13];
    const float* bo   = (const float*)d_in[14];
    float* out = (float*)d_out;

    float* pre;  cudaGetSymbolAddress((void**)&pre,  g_pre);
    float* hall; cudaGetSymbolAddress((void**)&hall, g_h);
    float* wt;   cudaGetSymbolAddress((void**)&wt,   g_wt);

    const int REC_SMEM = (32 * HS_STRIDE + 16 * 128) * 4;  // 74752 B
    cudaFuncSetAttribute(k_rec, cudaFuncAttributeMaxDynamicSharedMemorySize, REC_SMEM);

    k_pre<<<dim3(512, 12), 256>>>(x, Wzx, Wrx, Whx, pre);
    k_tr <<<dim3(16, 48), 256>>>(Wzh, Wrh, Whh, wt);
    k_rec<<<128, 256, REC_SMEM>>>(pre, wt, bz, br, bh, hall);
    k_out<<<dim3(512, 4), 256>>>(hall, Wo, bo, out);
    (void)in_sizes; (void)n_in; (void)out_size;
}

// round 7
// speedup vs baseline: 1.4058x; 1.4058x over previous
#include <cuda_runtime.h>
#include <math.h>
#include <stdint.h>

#define B_   512
#define T_   128
#define DIN  256
#define U_   512
#define NPRE 1536   // [z | r | h] precomputed input projections

// Scratch (static device arrays — allocation-free rule)
__device__ float g_pre[(size_t)T_ * B_ * NPRE];  // [t][b][1536]
__device__ float g_h  [(size_t)T_ * B_ * U_];    // [t][b][512]

typedef unsigned long long ull;

__device__ __forceinline__ ull dup2(float v) {
    ull r; asm("mov.b64 %0, {%1, %1};" : "=l"(r) : "f"(v)); return r;
}
__device__ __forceinline__ ull pack2(float lo, float hi) {
    ull r; asm("mov.b64 %0, {%1, %2};" : "=l"(r) : "f"(lo), "f"(hi)); return r;
}
__device__ __forceinline__ void fma2(ull& d, ull a, ull b) {
    asm("fma.rn.f32x2 %0, %1, %2, %0;" : "+l"(d) : "l"(a), "l"(b));
}
__device__ __forceinline__ ull mul2(ull a, ull b) {
    ull r; asm("mul.rn.f32x2 %0, %1, %2;" : "=l"(r) : "l"(a), "l"(b)); return r;
}
__device__ __forceinline__ float2 unpk(ull v) {
    float2 f; asm("mov.b64 {%0, %1}, %2;" : "=f"(f.x), "=f"(f.y) : "l"(v)); return f;
}
__device__ __forceinline__ float sigf(float x) {
    return 1.0f / (1.0f + expf(-x));
}
__device__ __forceinline__ uint32_t smem_u32(const void* p) {
    uint32_t a;
    asm("{ .reg .u64 t; cvta.to.shared.u64 t, %1; cvt.u32.u64 %0, t; }" : "=r"(a) : "l"(p));
    return a;
}
__device__ __forceinline__ void st_rem2(uint32_t laddr, uint32_t rank, ull a, ull b) {
    uint32_t ra;
    asm volatile("mapa.shared::cluster.u32 %0, %1, %2;" : "=r"(ra) : "r"(laddr), "r"(rank));
    asm volatile("st.shared::cluster.v2.b64 [%0], {%1, %2};" :: "r"(ra), "l"(a), "l"(b) : "memory");
}
__device__ __forceinline__ void cluster_sync() {
    asm volatile("barrier.cluster.arrive.aligned;" ::: "memory");
    asm volatile("barrier.cluster.wait.aligned;" ::: "memory");
}

// ============================================================================
// Phase 1: pre[t][b][0:1536] = x[b][t][:] @ [Wzx | Wrx | Whx]
// M=65536 (m = b*128 + t), N=1536, K=256. 128x128 tiles, BK=8, 8x8/thread,
// f32x2, double-buffered global loads.
// ============================================================================
__global__ void __launch_bounds__(256) k_pre(
    const float* __restrict__ X,
    const float* __restrict__ Wzx, const float* __restrict__ Wrx, const float* __restrict__ Whx,
    float* __restrict__ pre)
{
    __shared__ __align__(16) float As[8][128];   // [k][m] transposed
    __shared__ __align__(16) float Bs[8][128];   // [k][n]

    const int tid = threadIdx.x;
    const int bm = blockIdx.x, bn = blockIdx.y;
    const int gate = (bn * 128) >> 9;
    const float* Wg = gate == 0 ? Wzx : (gate == 1 ? Wrx : Whx);
    const int ncol0 = bn * 128 - gate * 512;

    const int tx = tid & 15, ty = tid >> 4;
    const int m0 = ty * 8, n0 = tx * 8;

    const int arow = tid >> 1, acol = (tid & 1) * 4;
    const int brow = tid >> 5, bcol = (tid & 31) * 4;
    const float* Ap = X  + (size_t)(bm * 128 + arow) * DIN + acol;
    const float* Bp = Wg + (size_t)brow * U_ + ncol0 + bcol;

    ull acc[8][4];
    #pragma unroll
    for (int j = 0; j < 8; j++)
        #pragma unroll
        for (int p = 0; p < 4; p++) acc[j][p] = 0ull;

    float4 av = *(const float4*)(Ap);
    float4 bv = *(const float4*)(Bp);

    for (int k0 = 0; k0 < DIN; k0 += 8) {
        As[acol + 0][arow] = av.x; As[acol + 1][arow] = av.y;
        As[acol + 2][arow] = av.z; As[acol + 3][arow] = av.w;
        *(float4*)&Bs[brow][bcol] = bv;
        __syncthreads();
        if (k0 + 8 < DIN) {
            av = *(const float4*)(Ap + k0 + 8);
            bv = *(const float4*)(Bp + (size_t)(k0 + 8) * U_);
        }
        #pragma unroll
        for (int kk = 0; kk < 8; kk++) {
            ulonglong2 a01 = *(const ulonglong2*)&As[kk][m0];
            ulonglong2 a23 = *(const ulonglong2*)&As[kk][m0 + 4];
            ull ap[4] = {a01.x, a01.y, a23.x, a23.y};
            float4 b0 = *(const float4*)&Bs[kk][n0];
            float4 b1 = *(const float4*)&Bs[kk][n0 + 4];
            ull bd[8] = {dup2(b0.x), dup2(b0.y), dup2(b0.z), dup2(b0.w),
                         dup2(b1.x), dup2(b1.y), dup2(b1.z), dup2(b1.w)};
            #pragma unroll
            for (int j = 0; j < 8; j++)
                #pragma unroll
                for (int p = 0; p < 4; p++) fma2(acc[j][p], bd[j], ap[p]);
        }
        __syncthreads();
    }

    const int gn0 = bn * 128 + n0;
    #pragma unroll
    for (int m = 0; m < 8; m++) {
        int gm = bm * 128 + m0 + m;
        int b = gm >> 7, t = gm & 127;            // X row m = b*T + t
        float* dst = pre + (size_t)(t * B_ + b) * NPRE + gn0;
        float v[8];
        #pragma unroll
        for (int j = 0; j < 8; j++) { float2 f = unpk(acc[j][m >> 1]); v[j] = (m & 1) ? f.y : f.x; }
        *(float4*)(dst)     = make_float4(v[0], v[1], v[2], v[3]);
        *(float4*)(dst + 4) = make_float4(v[4], v[5], v[6], v[7]);
    }
}

// ============================================================================
// Phase 2: the recurrence. 32 clusters x 4 CTAs, 512 threads/CTA (16 warps).
// Cluster owns 16 batch rows; rank j owns cols [j*128,(j+1)*128) of z, r, h.
// hs/rhs [k][m] transposed (LDS.128 broadcast); weights coalesced float2/float
// column loads (R5 layout), ping-pong 8-deep. DSMEM broadcast to 3 peers.
// Per-thread: zr = 2 cols x 4 rows, h = 1 col x 4 rows.
// ============================================================================
#define ZR_STEP(BUF, KB)                                                        \
    do {                                                                        \
        _Pragma("unroll")                                                       \
        for (int i_ = 0; i_ < 8; i_++) {                                        \
            const float* hp_ = hs + (size_t)((KB) + i_) * 16 + rh4;             \
            ulonglong2 h01_ = *(const ulonglong2*)hp_;                          \
            ull w0_ = dup2(BUF[i_].x), w1_ = dup2(BUF[i_].y);                   \
            fma2(acc[0][0], w0_, h01_.x); fma2(acc[0][1], w0_, h01_.y);         \
            fma2(acc[1][0], w1_, h01_.x); fma2(acc[1][1], w1_, h01_.y);         \
        }                                                                       \
    } while (0)

#define H_STEP(BUF, KB)                                                         \
    do {                                                                        \
        _Pragma("unroll")                                                       \
        for (int i_ = 0; i_ < 8; i_++) {                                        \
            const float* rp_ = rhs + (size_t)((KB) + i_) * 16 + m0h;            \
            ulonglong2 r01_ = *(const ulonglong2*)rp_;                          \
            ull w_ = dup2(BUF[i_]);                                             \
            fma2(acch[0], w_, r01_.x); fma2(acch[1], w_, r01_.y);               \
        }                                                                       \
    } while (0)

__global__ void __launch_bounds__(512) __cluster_dims__(4, 1, 1) k_rec(
    const float* __restrict__ pre,
    const float* __restrict__ Wzh, const float* __restrict__ Wrh, const float* __restrict__ Whh,
    const float* __restrict__ bz, const float* __restrict__ br, const float* __restrict__ bh,
    float* __restrict__ hall)
{
    extern __shared__ __align__(16) float smf[];
    float* hs  = smf;           // [512][16]  h,   [k][m]
    float* rhs = smf + 8192;    // [512][16]  r*h, [k][m]
    float* zsm = smf + 16384;   // [16][128]  z,   [m][c_local]

    const int tid   = threadIdx.x;
    const int rank  = blockIdx.x & 3;
    const int cid   = blockIdx.x >> 2;
    const int b0    = cid * 16;
    const int jbase = rank * 128;

    const uint32_t sb      = smem_u32(smf);
    const uint32_t RHS_OFF = 32768;

    // zr-phase mapping: 4-row group x 2 cols; zsel picks z vs r
    const int rh4  = ((tid >> 7) & 3) * 4;
    const int cp   = tid & 63;
    const int zsel = (tid >> 6) & 1;
    const int colw = jbase + 2 * cp;
    const float* Wzr = zsel ? Wrh : Wzh;
    const float2 bias2 = *(const float2*)((zsel ? br : bz) + colw);
    const int precolzr = (zsel ? 512 : 0) + colw;

    // h-phase mapping: 4-row group x 1 col
    const int hc  = tid & 127;
    const int m0h = ((tid >> 7) & 3) * 4;
    const int k0h = jbase + hc;
    const float bhc = bh[k0h];

    for (int i = tid; i < 8192; i += 512) hs[i] = 0.0f;
    cluster_sync();

    for (int t = 0; t < T_; t++) {
        const float* pre_t = pre + (size_t)(t * B_ + b0) * NPRE;

        // prefetch input-projection values for zr elementwise
        float2 pz[4];
        #pragma unroll
        for (int mi = 0; mi < 4; mi++)
            pz[mi] = *(const float2*)(pre_t + (size_t)(rh4 + mi) * NPRE + precolzr);

        // ---------------- zr GEMM: 2 cols x 4 rows, K=512 ----------------
        ull acc[2][2];
        #pragma unroll
        for (int j = 0; j < 2; j++)
            #pragma unroll
            for (int p = 0; p < 2; p++) acc[j][p] = 0ull;

        {
            const float* wp = Wzr + colw;
            float2 wa[8], wb[8];
            #pragma unroll
            for (int i = 0; i < 8; i++) wa[i] = *(const float2*)(wp + (size_t)i * U_);
            for (int kb = 0; kb < 512; kb += 16) {
                #pragma unroll
                for (int i = 0; i < 8; i++) wb[i] = *(const float2*)(wp + (size_t)(kb + 8 + i) * U_);
                ZR_STEP(wa, kb);
                if (kb + 16 < 512) {
                    #pragma unroll
                    for (int i = 0; i < 8; i++) wa[i] = *(const float2*)(wp + (size_t)(kb + 16 + i) * U_);
                }
                ZR_STEP(wb, kb + 8);
            }
        }

        // ---------------- z / r elementwise ----------------
        float v0[4], v1[4];
        #pragma unroll
        for (int p = 0; p < 2; p++) {
            float2 f0 = unpk(acc[0][p]), f1 = unpk(acc[1][p]);
            v0[2 * p]     = sigf(f0.x + pz[2 * p].x     + bias2.x);
            v0[2 * p + 1] = sigf(f0.y + pz[2 * p + 1].x + bias2.x);
            v1[2 * p]     = sigf(f1.x + pz[2 * p].y     + bias2.y);
            v1[2 * p + 1] = sigf(f1.y + pz[2 * p + 1].y + bias2.y);
        }
        if (!zsel) {
            // z -> local zsm (z cols == own h cols, no exchange needed)
            #pragma unroll
            for (int mi = 0; mi < 4; mi++)
                *(float2*)(zsm + (size_t)(rh4 + mi) * 128 + 2 * cp) = make_float2(v0[mi], v1[mi]);
        } else {
            // r -> rhs[k][m] = r * h, local + 3 peers
            #pragma unroll
            for (int j = 0; j < 2; j++) {
                const int k0 = colw + j;
                float* hp = hs + (size_t)k0 * 16 + rh4;
                ulonglong2 h01 = *(const ulonglong2*)hp;
                const float* vv = j ? v1 : v0;
                ull r0 = mul2(pack2(vv[0], vv[1]), h01.x);
                ull r1 = mul2(pack2(vv[2], vv[3]), h01.y);
                float* rp = rhs + (size_t)k0 * 16 + rh4;
                *(ulonglong2*)rp = make_ulonglong2(r0, r1);
                const uint32_t la = sb + RHS_OFF + (uint32_t)(k0 * 16 + rh4) * 4;
                #pragma unroll
                for (int d = 1; d < 4; d++)
                    st_rem2(la, (rank + d) & 3, r0, r1);
            }
        }

        cluster_sync();   // rhs complete everywhere; zsm complete locally

        // prefetch pre_h
        float phh[4];
        #pragma unroll
        for (int mi = 0; mi < 4; mi++)
            phh[mi] = pre_t[(size_t)(m0h + mi) * NPRE + 1024 + k0h];

        // ---------------- h GEMM: 1 col x 4 rows, K=512 ----------------
        ull acch[2];
        acch[0] = 0ull; acch[1] = 0ull;
        {
            const float* wp = Whh + k0h;
            float wa[8], wb[8];
            #pragma unroll
            for (int i = 0; i < 8; i++) wa[i] = wp[(size_t)i * U_];
            for (int kb = 0; kb < 512; kb += 16) {
                #pragma unroll
                for (int i = 0; i < 8; i++) wb[i] = wp[(size_t)(kb + 8 + i) * U_];
                H_STEP(wa, kb);
                if (kb + 16 < 512) {
                    #pragma unroll
                    for (int i = 0; i < 8; i++) wa[i] = wp[(size_t)(kb + 16 + i) * U_];
                }
                H_STEP(wb, kb + 8);
            }
        }

        // ---------------- h elementwise + writeback ----------------
        float hcand[4];
        #pragma unroll
        for (int p = 0; p < 2; p++) {
            float2 f = unpk(acch[p]);
            hcand[2 * p]     = tanhf(f.x + phh[2 * p]     + bhc);
            hcand[2 * p + 1] = tanhf(f.y + phh[2 * p + 1] + bhc);
        }
        float* hp = hs + (size_t)k0h * 16 + m0h;
        ulonglong2 o01 = *(const ulonglong2*)hp;
        float ho[4];
        { float2 f;
          f = unpk(o01.x); ho[0] = f.x; ho[1] = f.y;
          f = unpk(o01.y); ho[2] = f.x; ho[3] = f.y; }
        float hn[4];
        #pragma unroll
        for (int mi = 0; mi < 4; mi++) {
            float z = zsm[(size_t)(m0h + mi) * 128 + hc];
            hn[mi] = ho[mi] + z * (hcand[mi] - ho[mi]);
        }
        ull n0 = pack2(hn[0], hn[1]), n1 = pack2(hn[2], hn[3]);
        *(ulonglong2*)hp = make_ulonglong2(n0, n1);
        const uint32_t la = sb + (uint32_t)(k0h * 16 + m0h) * 4;
        #pragma unroll
        for (int d = 1; d < 4; d++)
            st_rem2(la, (rank + d) & 3, n0, n1);
        float* gh = hall + (size_t)(t * B_ + b0 + m0h) * U_ + k0h;
        #pragma unroll
        for (int mi = 0; mi < 4; mi++)
            gh[(size_t)mi * U_] = hn[mi];

        cluster_sync();   // hs updated everywhere for next step
    }
}

// ============================================================================
// Phase 3: out[b][t][:] = g_h[t][b][:] @ W_o + b_o
// M=65536 (m' = t*512 + b), N=512, K=512. Double-buffered.
// ============================================================================
__global__ void __launch_bounds__(256) k_out(
    const float* __restrict__ H, const float* __restrict__ Wo, const float* __restrict__ bo,
    float* __restrict__ out)
{
    __shared__ __align__(16) float As[8][128];
    __shared__ __align__(16) float Bs[8][128];

    const int tid = threadIdx.x;
    const int bm = blockIdx.x, bn = blockIdx.y;

    const int tx = tid & 15, ty = tid >> 4;
    const int m0 = ty * 8, n0 = tx * 8;

    const int arow = tid >> 1, acol = (tid & 1) * 4;
    const int brow = tid >> 5, bcol = (tid & 31) * 4;
    const float* Ap = H  + (size_t)(bm * 128 + arow) * U_ + acol;
    const float* Bp = Wo + (size_t)brow * U_ + bn * 128 + bcol;

    ull acc[8][4];
    #pragma unroll
    for (int j = 0; j < 8; j++)
        #pragma unroll
        for (int p = 0; p < 4; p++) acc[j][p] = 0ull;

    float4 av = *(const float4*)(Ap);
    float4 bv = *(const float4*)(Bp);

    for (int k0 = 0; k0 < U_; k0 += 8) {
        As[acol + 0][arow] = av.x; As[acol + 1][arow] = av.y;
        As[acol + 2][arow] = av.z; As[acol + 3][arow] = av.w;
        *(float4*)&Bs[brow][bcol] = bv;
        __syncthreads();
        if (k0 + 8 < U_) {
            av = *(const float4*)(Ap + k0 + 8);
            bv = *(const float4*)(Bp + (size_t)(k0 + 8) * U_);
        }
        #pragma unroll
        for (int kk = 0; kk < 8; kk++) {
            ulonglong2 a01 = *(const ulonglong2*)&As[kk][m0];
            ulonglong2 a23 = *(const ulonglong2*)&As[kk][m0 + 4];
            ull ap[4] = {a01.x, a01.y, a23.x, a23.y};
            float4 b0 = *(const float4*)&Bs[kk][n0];
            float4 b1 = *(const float4*)&Bs[kk][n0 + 4];
            ull bd[8] = {dup2(b0.x), dup2(b0.y), dup2(b0.z), dup2(b0.w),
                         dup2(b1.x), dup2(b1.y), dup2(b1.z), dup2(b1.w)};
            #pragma unroll
            for (int j = 0; j < 8; j++)
                #pragma unroll
                for (int p = 0; p < 4; p++) fma2(acc[j][p], bd[j], ap[p]);
        }
        __syncthreads();
    }

    const int gn0 = bn * 128 + n0;
    const float4 bo0 = *(const float4*)(bo + gn0);
    const float4 bo1 = *(const float4*)(bo + gn0 + 4);
    #pragma unroll
    for (int m = 0; m < 8; m++) {
        int mm = bm * 128 + m0 + m;            // h_all row = t*512 + b
        int b = mm & 511, t = mm >> 9;
        float* dst = out + (size_t)(b * T_ + t) * U_ + gn0;
        float v[8];
        #pragma unroll
        for (int j = 0; j < 8; j++) { float2 f = unpk(acc[j][m >> 1]); v[j] = (m & 1) ? f.y : f.x; }
        *(float4*)(dst)     = make_float4(v[0] + bo0.x, v[1] + bo0.y, v[2] + bo0.z, v[3] + bo0.w);
        *(float4*)(dst + 4) = make_float4(v[4] + bo1.x, v[5] + bo1.y, v[6] + bo1.z, v[7] + bo1.w);
    }
}

// ============================================================================
extern "C" void kernel_launch(void* const* d_in, const int* in_sizes, int n_in,
                              void* d_out, int out_size)
{
    const float* x    = (const float*)d_in[0];
    const float* Wzx  = (const float*)d_in[1];
    const float* Wrx  = (const float*)d_in[2];
    const float* Whx  = (const float*)d_in[3];
    const float* Wzh  = (const float*)d_in[4];
    const float* Wrh  = (const float*)d_in[5];
    const float* Whh  = (const float*)d_in[6];
    const float* bz   = (const float*)d_in[7];
    const float* br   = (const float*)d_in[8];
    const float* bh   = (const float*)d_in[9];
    // d_in[10..12] = W_q, W_k, W_v : dead code in the reference (attn unused)
    const float* Wo   = (const float*)d_in[13];
    const float* bo   = (const float*)d_in[14];
    float* out = (float*)d_out;

    float* pre;  cudaGetSymbolAddress((void**)&pre,  g_pre);
    float* hall; cudaGetSymbolAddress((void**)&hall, g_h);

    const int REC_SMEM = 73728;  // hs 32K + rhs 32K + zsm 8K
    cudaFuncSetAttribute(k_rec, cudaFuncAttributeMaxDynamicSharedMemorySize, REC_SMEM);

    k_pre<<<dim3(512, 12), 256>>>(x, Wzx, Wrx, Whx, pre);
    k_rec<<<128, 512, REC_SMEM>>>(pre, Wzh, Wrh, Whh, bz, br, bh, hall);
    k_out<<<dim3(512, 4), 256>>>(hall, Wo, bo, out);
    (void)in_sizes; (void)n_in; (void)out_size;
}

// round 8
// speedup vs baseline: 1.6506x; 1.1742x over previous
#include <cuda_runtime.h>
#include <math.h>
#include <stdint.h>

#define B_   512
#define T_   128
#define DIN  256
#define U_   512
#define NPRE 1536   // [z | r | h] precomputed input projections

// Scratch (static device arrays — allocation-free rule)
__device__ float g_pre[(size_t)T_ * B_ * NPRE];  // [t][b][1536]
__device__ float g_h  [(size_t)T_ * B_ * U_];    // [t][b][512]

typedef unsigned long long ull;

__device__ __forceinline__ ull dup2(float v) {
    ull r; asm("mov.b64 %0, {%1, %1};" : "=l"(r) : "f"(v)); return r;
}
__device__ __forceinline__ ull pack2(float lo, float hi) {
    ull r; asm("mov.b64 %0, {%1, %2};" : "=l"(r) : "f"(lo), "f"(hi)); return r;
}
__device__ __forceinline__ void fma2(ull& d, ull a, ull b) {
    asm("fma.rn.f32x2 %0, %1, %2, %0;" : "+l"(d) : "l"(a), "l"(b));
}
__device__ __forceinline__ ull mul2(ull a, ull b) {
    ull r; asm("mul.rn.f32x2 %0, %1, %2;" : "=l"(r) : "l"(a), "l"(b)); return r;
}
__device__ __forceinline__ float2 unpk(ull v) {
    float2 f; asm("mov.b64 {%0, %1}, %2;" : "=f"(f.x), "=f"(f.y) : "l"(v)); return f;
}
__device__ __forceinline__ float sigf(float x) {
    return 1.0f / (1.0f + expf(-x));
}
__device__ __forceinline__ uint32_t smem_u32(const void* p) {
    uint32_t a;
    asm("{ .reg .u64 t; cvta.to.shared.u64 t, %1; cvt.u32.u64 %0, t; }" : "=r"(a) : "l"(p));
    return a;
}
__device__ __forceinline__ void st_rem2(uint32_t laddr, uint32_t rank, ull a, ull b) {
    uint32_t ra;
    asm volatile("mapa.shared::cluster.u32 %0, %1, %2;" : "=r"(ra) : "r"(laddr), "r"(rank));
    asm volatile("st.shared::cluster.v2.b64 [%0], {%1, %2};" :: "r"(ra), "l"(a), "l"(b) : "memory");
}
__device__ __forceinline__ void cluster_sync() {
    asm volatile("barrier.cluster.arrive.aligned;" ::: "memory");
    asm volatile("barrier.cluster.wait.aligned;" ::: "memory");
}

// ============================================================================
// Phase 1: pre[t][b][0:1536] = x[b][t][:] @ [Wzx | Wrx | Whx]
// ============================================================================
__global__ void __launch_bounds__(256) k_pre(
    const float* __restrict__ X,
    const float* __restrict__ Wzx, const float* __restrict__ Wrx, const float* __restrict__ Whx,
    float* __restrict__ pre)
{
    __shared__ __align__(16) float As[8][128];
    __shared__ __align__(16) float Bs[8][128];

    const int tid = threadIdx.x;
    const int bm = blockIdx.x, bn = blockIdx.y;
    const int gate = (bn * 128) >> 9;
    const float* Wg = gate == 0 ? Wzx : (gate == 1 ? Wrx : Whx);
    const int ncol0 = bn * 128 - gate * 512;

    const int tx = tid & 15, ty = tid >> 4;
    const int m0 = ty * 8, n0 = tx * 8;

    const int arow = tid >> 1, acol = (tid & 1) * 4;
    const int brow = tid >> 5, bcol = (tid & 31) * 4;
    const float* Ap = X  + (size_t)(bm * 128 + arow) * DIN + acol;
    const float* Bp = Wg + (size_t)brow * U_ + ncol0 + bcol;

    ull acc[8][4];
    #pragma unroll
    for (int j = 0; j < 8; j++)
        #pragma unroll
        for (int p = 0; p < 4; p++) acc[j][p] = 0ull;

    float4 av = *(const float4*)(Ap);
    float4 bv = *(const float4*)(Bp);

    for (int k0 = 0; k0 < DIN; k0 += 8) {
        As[acol + 0][arow] = av.x; As[acol + 1][arow] = av.y;
        As[acol + 2][arow] = av.z; As[acol + 3][arow] = av.w;
        *(float4*)&Bs[brow][bcol] = bv;
        __syncthreads();
        if (k0 + 8 < DIN) {
            av = *(const float4*)(Ap + k0 + 8);
            bv = *(const float4*)(Bp + (size_t)(k0 + 8) * U_);
        }
        #pragma unroll
        for (int kk = 0; kk < 8; kk++) {
            ulonglong2 a01 = *(const ulonglong2*)&As[kk][m0];
            ulonglong2 a23 = *(const ulonglong2*)&As[kk][m0 + 4];
            ull ap[4] = {a01.x, a01.y, a23.x, a23.y};
            float4 b0 = *(const float4*)&Bs[kk][n0];
            float4 b1 = *(const float4*)&Bs[kk][n0 + 4];
            ull bd[8] = {dup2(b0.x), dup2(b0.y), dup2(b0.z), dup2(b0.w),
                         dup2(b1.x), dup2(b1.y), dup2(b1.z), dup2(b1.w)};
            #pragma unroll
            for (int j = 0; j < 8; j++)
                #pragma unroll
                for (int p = 0; p < 4; p++) fma2(acc[j][p], bd[j], ap[p]);
        }
        __syncthreads();
    }

    const int gn0 = bn * 128 + n0;
    #pragma unroll
    for (int m = 0; m < 8; m++) {
        int gm = bm * 128 + m0 + m;
        int b = gm >> 7, t = gm & 127;
        float* dst = pre + (size_t)(t * B_ + b) * NPRE + gn0;
        float v[8];
        #pragma unroll
        for (int j = 0; j < 8; j++) { float2 f = unpk(acc[j][m >> 1]); v[j] = (m & 1) ? f.y : f.x; }
        *(float4*)(dst)     = make_float4(v[0], v[1], v[2], v[3]);
        *(float4*)(dst + 4) = make_float4(v[4], v[5], v[6], v[7]);
    }
}

// ============================================================================
// Phase 2: recurrence. 32 clusters x 4 CTAs, 256 threads.
// K-split GEMMs: thread = (k-half, slot). zr: slot = 2 cols x 16 rows;
// h: slot = 1 col x 16 rows. Partials combined via SMEM pbuf, then
// elementwise + DSMEM broadcast of r*h and h to the 3 peer CTAs.
// SMEM: hs[512][16] | rhs[512][16] | zsm[16][128] | pb[2][16][256]
// ============================================================================
#define ZR_STEP16(BUF, KB)                                                      \
    do {                                                                        \
        _Pragma("unroll")                                                       \
        for (int i_ = 0; i_ < 8; i_++) {                                        \
            const float* hp_ = hs + (size_t)((KB) + i_) * 16;                   \
            ulonglong2 ha_ = *(const ulonglong2*)hp_;                           \
            ulonglong2 hb_ = *(const ulonglong2*)(hp_ + 4);                     \
            ulonglong2 hc_ = *(const ulonglong2*)(hp_ + 8);                     \
            ulonglong2 hd_ = *(const ulonglong2*)(hp_ + 12);                    \
            ull w0_ = dup2(BUF[i_].x), w1_ = dup2(BUF[i_].y);                   \
            fma2(acc[0][0], w0_, ha_.x); fma2(acc[0][1], w0_, ha_.y);           \
            fma2(acc[0][2], w0_, hb_.x); fma2(acc[0][3], w0_, hb_.y);           \
            fma2(acc[0][4], w0_, hc_.x); fma2(acc[0][5], w0_, hc_.y);           \
            fma2(acc[0][6], w0_, hd_.x); fma2(acc[0][7], w0_, hd_.y);           \
            fma2(acc[1][0], w1_, ha_.x); fma2(acc[1][1], w1_, ha_.y);           \
            fma2(acc[1][2], w1_, hb_.x); fma2(acc[1][3], w1_, hb_.y);           \
            fma2(acc[1][4], w1_, hc_.x); fma2(acc[1][5], w1_, hc_.y);           \
            fma2(acc[1][6], w1_, hd_.x); fma2(acc[1][7], w1_, hd_.y);           \
        }                                                                       \
    } while (0)

#define H_STEP16(BUF, KB)                                                       \
    do {                                                                        \
        _Pragma("unroll")                                                       \
        for (int i_ = 0; i_ < 8; i_++) {                                        \
            const float* rp_ = rhs + (size_t)((KB) + i_) * 16;                  \
            ulonglong2 ra_ = *(const ulonglong2*)rp_;                           \
            ulonglong2 rb_ = *(const ulonglong2*)(rp_ + 4);                     \
            ulonglong2 rc_ = *(const ulonglong2*)(rp_ + 8);                     \
            ulonglong2 rd_ = *(const ulonglong2*)(rp_ + 12);                    \
            ull w_ = dup2(BUF[i_]);                                             \
            fma2(acch[0], w_, ra_.x); fma2(acch[1], w_, ra_.y);                 \
            fma2(acch[2], w_, rb_.x); fma2(acch[3], w_, rb_.y);                 \
            fma2(acch[4], w_, rc_.x); fma2(acch[5], w_, rc_.y);                 \
            fma2(acch[6], w_, rd_.x); fma2(acch[7], w_, rd_.y);                 \
        }                                                                       \
    } while (0)

__global__ void __launch_bounds__(256) __cluster_dims__(4, 1, 1) k_rec(
    const float* __restrict__ pre,
    const float* __restrict__ Wzh, const float* __restrict__ Wrh, const float* __restrict__ Whh,
    const float* __restrict__ bz, const float* __restrict__ br, const float* __restrict__ bh,
    float* __restrict__ hall)
{
    extern __shared__ __align__(16) float smf[];
    float* hs  = smf;            // [512][16]
    float* rhs = smf + 8192;     // [512][16]
    float* zsm = smf + 16384;    // [16][128]
    float* pb  = smf + 18432;    // [2][16][256] partial sums

    const int tid   = threadIdx.x;
    const int rank  = blockIdx.x & 3;
    const int cid   = blockIdx.x >> 2;
    const int b0    = cid * 16;
    const int jbase = rank * 128;

    const uint32_t sb      = smem_u32(smf);
    const uint32_t RHS_OFF = 32768;

    // GEMM-phase mapping: (k-half, slot)
    const int kh   = tid >> 7;           // 0/1 : k in [kh*256, kh*256+256)
    const int kb0  = kh * 256;
    const int slot = tid & 127;
    const int zsel = slot >> 6;          // zr: 0=z cols, 1=r cols
    const int cp   = slot & 63;
    const int colw = jbase + 2 * cp;
    const float* wzr = (zsel ? Wrh : Wzh) + colw;     // 2 cols, rows k
    const float* wph = Whh + jbase + slot;            // 1 col,  rows k

    // zr-combine mapping: thread = one of 256 zr outputs cols, all 16 rows
    const int czsel = tid >> 7;
    const int ccc   = tid & 127;
    const int cidx  = tid;               // col index in pb (0..255)
    const int cprecol = czsel ? (512 + jbase + ccc) : (jbase + ccc);
    const float cbias = (czsel ? br : bz)[jbase + ccc];
    const int rk0 = jbase + ccc;         // r-thread: hs/rhs row (k index)

    // h-combine mapping: thread = 1 col x 8 rows
    const int hcc = tid & 127, hm0 = (tid >> 7) * 8;
    const int k0h = jbase + hcc;
    const float bhc = bh[k0h];

    for (int i = tid; i < 8192; i += 256) hs[i] = 0.0f;
    cluster_sync();

    for (int t = 0; t < T_; t++) {
        const float* pre_t = pre + (size_t)(t * B_ + b0) * NPRE;

        // prefetch combine-phase inputs (global, long latency — issue early)
        float pzc[16];
        #pragma unroll
        for (int m = 0; m < 16; m++) pzc[m] = pre_t[(size_t)m * NPRE + cprecol];
        float phh[8];
        #pragma unroll
        for (int mi = 0; mi < 8; mi++)
            phh[mi] = pre_t[(size_t)(hm0 + mi) * NPRE + 1024 + k0h];

        // ---------------- zr GEMM (half-K): 2 cols x 16 rows ----------------
        ull acc[2][8];
        #pragma unroll
        for (int j = 0; j < 2; j++)
            #pragma unroll
            for (int q = 0; q < 8; q++) acc[j][q] = 0ull;
        {
            const float* wp = wzr + (size_t)kb0 * U_;
            float2 wa[8], wb[8];
            #pragma unroll
            for (int i = 0; i < 8; i++) wa[i] = *(const float2*)(wp + (size_t)i * U_);
            for (int kb = 0; kb < 256; kb += 16) {
                #pragma unroll
                for (int i = 0; i < 8; i++) wb[i] = *(const float2*)(wp + (size_t)(kb + 8 + i) * U_);
                ZR_STEP16(wa, kb0 + kb);
                if (kb + 16 < 256) {
                    #pragma unroll
                    for (int i = 0; i < 8; i++) wa[i] = *(const float2*)(wp + (size_t)(kb + 16 + i) * U_);
                }
                ZR_STEP16(wb, kb0 + kb + 8);
            }
        }
        // store partials: pb[kh][m][zsel*128 + 2cp + j]
        {
            float* pbk = pb + kh * 4096;
            const int c0 = zsel * 128 + 2 * cp;
            #pragma unroll
            for (int q = 0; q < 8; q++) {
                float2 f0 = unpk(acc[0][q]);
                float2 f1 = unpk(acc[1][q]);
                pbk[(2 * q)     * 256 + c0]     = f0.x;
                pbk[(2 * q + 1) * 256 + c0]     = f0.y;
                pbk[(2 * q)     * 256 + c0 + 1] = f1.x;
                pbk[(2 * q + 1) * 256 + c0 + 1] = f1.y;
            }
        }
        __syncthreads();

        // ---------------- combine z / r ----------------
        {
            float v[16];
            #pragma unroll
            for (int m = 0; m < 16; m++)
                v[m] = sigf(pb[m * 256 + cidx] + pb[4096 + m * 256 + cidx] + pzc[m] + cbias);
            if (!czsel) {
                #pragma unroll
                for (int m = 0; m < 16; m++) zsm[m * 128 + ccc] = v[m];
            } else {
                const float* hp = hs + (size_t)rk0 * 16;
                ulonglong2 a0 = *(const ulonglong2*)hp;
                ulonglong2 a1 = *(const ulonglong2*)(hp + 4);
                ulonglong2 a2 = *(const ulonglong2*)(hp + 8);
                ulonglong2 a3 = *(const ulonglong2*)(hp + 12);
                ull r0 = mul2(pack2(v[0],  v[1]),  a0.x);
                ull r1 = mul2(pack2(v[2],  v[3]),  a0.y);
                ull r2 = mul2(pack2(v[4],  v[5]),  a1.x);
                ull r3 = mul2(pack2(v[6],  v[7]),  a1.y);
                ull r4 = mul2(pack2(v[8],  v[9]),  a2.x);
                ull r5 = mul2(pack2(v[10], v[11]), a2.y);
                ull r6 = mul2(pack2(v[12], v[13]), a3.x);
                ull r7 = mul2(pack2(v[14], v[15]), a3.y);
                float* rp = rhs + (size_t)rk0 * 16;
                *(ulonglong2*)rp        = make_ulonglong2(r0, r1);
                *(ulonglong2*)(rp + 4)  = make_ulonglong2(r2, r3);
                *(ulonglong2*)(rp + 8)  = make_ulonglong2(r4, r5);
                *(ulonglong2*)(rp + 12) = make_ulonglong2(r6, r7);
                const uint32_t la = sb + RHS_OFF + (uint32_t)rk0 * 64;
                #pragma unroll
                for (int d = 1; d < 4; d++) {
                    const uint32_t pr = (rank + d) & 3;
                    st_rem2(la,      pr, r0, r1);
                    st_rem2(la + 16, pr, r2, r3);
                    st_rem2(la + 32, pr, r4, r5);
                    st_rem2(la + 48, pr, r6, r7);
                }
            }
        }
        cluster_sync();   // rhs complete everywhere; zsm local

        // ---------------- h GEMM (half-K): 1 col x 16 rows ----------------
        ull acch[8];
        #pragma unroll
        for (int q = 0; q < 8; q++) acch[q] = 0ull;
        {
            const float* wp = wph + (size_t)kb0 * U_;
            float wa[8], wb[8];
            #pragma unroll
            for (int i = 0; i < 8; i++) wa[i] = wp[(size_t)i * U_];
            for (int kb = 0; kb < 256; kb += 16) {
                #pragma unroll
                for (int i = 0; i < 8; i++) wb[i] = wp[(size_t)(kb + 8 + i) * U_];
                H_STEP16(wa, kb0 + kb);
                if (kb + 16 < 256) {
                    #pragma unroll
                    for (int i = 0; i < 8; i++) wa[i] = wp[(size_t)(kb + 16 + i) * U_];
                }
                H_STEP16(wb, kb0 + kb + 8);
            }
        }
        // store partials: pb[kh][m][slot]
        {
            float* pbk = pb + kh * 4096;
            #pragma unroll
            for (int q = 0; q < 8; q++) {
                float2 f = unpk(acch[q]);
                pbk[(2 * q)     * 256 + slot] = f.x;
                pbk[(2 * q + 1) * 256 + slot] = f.y;
            }
        }
        __syncthreads();

        // ---------------- combine h + writeback ----------------
        {
            float* hp = hs + (size_t)k0h * 16 + hm0;
            ulonglong2 o01 = *(const ulonglong2*)hp;
            ulonglong2 o23 = *(const ulonglong2*)(hp + 4);
            float ho[8];
            { float2 f;
              f = unpk(o01.x); ho[0] = f.x; ho[1] = f.y;
              f = unpk(o01.y); ho[2] = f.x; ho[3] = f.y;
              f = unpk(o23.x); ho[4] = f.x; ho[5] = f.y;
              f = unpk(o23.y); ho[6] = f.x; ho[7] = f.y; }
            float hn[8];
            #pragma unroll
            for (int mi = 0; mi < 8; mi++) {
                const int m = hm0 + mi;
                float s = pb[m * 256 + hcc] + pb[4096 + m * 256 + hcc] + phh[mi] + bhc;
                float hcand = tanhf(s);
                float z = zsm[m * 128 + hcc];
                hn[mi] = ho[mi] + z * (hcand - ho[mi]);
            }
            ull n0 = pack2(hn[0], hn[1]), n1 = pack2(hn[2], hn[3]);
            ull n2 = pack2(hn[4], hn[5]), n3 = pack2(hn[6], hn[7]);
            *(ulonglong2*)hp       = make_ulonglong2(n0, n1);
            *(ulonglong2*)(hp + 4) = make_ulonglong2(n2, n3);
            const uint32_t la = sb + (uint32_t)(k0h * 16 + hm0) * 4;
            #pragma unroll
            for (int d = 1; d < 4; d++) {
                const uint32_t pr = (rank + d) & 3;
                st_rem2(la,      pr, n0, n1);
                st_rem2(la + 16, pr, n2, n3);
            }
            float* gh = hall + (size_t)(t * B_ + b0 + hm0) * U_ + k0h;
            #pragma unroll
            for (int mi = 0; mi < 8; mi++)
                gh[(size_t)mi * U_] = hn[mi];
        }
        cluster_sync();   // hs updated everywhere for next step
    }
}

// ============================================================================
// Phase 3: out[b][t][:] = g_h[t][b][:] @ W_o + b_o
// ============================================================================
__global__ void __launch_bounds__(256) k_out(
    const float* __restrict__ H, const float* __restrict__ Wo, const float* __restrict__ bo,
    float* __restrict__ out)
{
    __shared__ __align__(16) float As[8][128];
    __shared__ __align__(16) float Bs[8][128];

    const int tid = threadIdx.x;
    const int bm = blockIdx.x, bn = blockIdx.y;

    const int tx = tid & 15, ty = tid >> 4;
    const int m0 = ty * 8, n0 = tx * 8;

    const int arow = tid >> 1, acol = (tid & 1) * 4;
    const int brow = tid >> 5, bcol = (tid & 31) * 4;
    const float* Ap = H  + (size_t)(bm * 128 + arow) * U_ + acol;
    const float* Bp = Wo + (size_t)brow * U_ + bn * 128 + bcol;

    ull acc[8][4];
    #pragma unroll
    for (int j = 0; j < 8; j++)
        #pragma unroll
        for (int p = 0; p < 4; p++) acc[j][p] = 0ull;

    float4 av = *(const float4*)(Ap);
    float4 bv = *(const float4*)(Bp);

    for (int k0 = 0; k0 < U_; k0 += 8) {
        As[acol + 0][arow] = av.x; As[acol + 1][arow] = av.y;
        As[acol + 2][arow] = av.z; As[acol + 3][arow] = av.w;
        *(float4*)&Bs[brow][bcol] = bv;
        __syncthreads();
        if (k0 + 8 < U_) {
            av = *(const float4*)(Ap + k0 + 8);
            bv = *(const float4*)(Bp + (size_t)(k0 + 8) * U_);
        }
        #pragma unroll
        for (int kk = 0; kk < 8; kk++) {
            ulonglong2 a01 = *(const ulonglong2*)&As[kk][m0];
            ulonglong2 a23 = *(const ulonglong2*)&As[kk][m0 + 4];
            ull ap[4] = {a01.x, a01.y, a23.x, a23.y};
            float4 b0 = *(const float4*)&Bs[kk][n0];
            float4 b1 = *(const float4*)&Bs[kk][n0 + 4];
            ull bd[8] = {dup2(b0.x), dup2(b0.y), dup2(b0.z), dup2(b0.w),
                         dup2(b1.x), dup2(b1.y), dup2(b1.z), dup2(b1.w)};
            #pragma unroll
            for (int j = 0; j < 8; j++)
                #pragma unroll
                for (int p = 0; p < 4; p++) fma2(acc[j][p], bd[j], ap[p]);
        }
        __syncthreads();
    }

    const int gn0 = bn * 128 + n0;
    const float4 bo0 = *(const float4*)(bo + gn0);
    const float4 bo1 = *(const float4*)(bo + gn0 + 4);
    #pragma unroll
    for (int m = 0; m < 8; m++) {
        int mm = bm * 128 + m0 + m;
        int b = mm & 511, t = mm >> 9;
        float* dst = out + (size_t)(b * T_ + t) * U_ + gn0;
        float v[8];
        #pragma unroll
        for (int j = 0; j < 8; j++) { float2 f = unpk(acc[j][m >> 1]); v[j] = (m & 1) ? f.y : f.x; }
        *(float4*)(dst)     = make_float4(v[0] + bo0.x, v[1] + bo0.y, v[2] + bo0.z, v[3] + bo0.w);
        *(float4*)(dst + 4) = make_float4(v[4] + bo1.x, v[5] + bo1.y, v[6] + bo1.z, v[7] + bo1.w);
    }
}

// ============================================================================
extern "C" void kernel_launch(void* const* d_in, const int* in_sizes, int n_in,
                              void* d_out, int out_size)
{
    const float* x    = (const float*)d_in[0];
    const float* Wzx  = (const float*)d_in[1];
    const float* Wrx  = (const float*)d_in[2];
    const float* Whx  = (const float*)d_in[3];
    const float* Wzh  = (const float*)d_in[4];
    const float* Wrh  = (const float*)d_in[5];
    const float* Whh  = (const float*)d_in[6];
    const float* bz   = (const float*)d_in[7];
    const float* br   = (const float*)d_in[8];
    const float* bh   = (const float*)d_in[9];
    // d_in[10..12] = W_q, W_k, W_v : dead code in the reference (attn unused)
    const float* Wo   = (const float*)d_in[13];
    const float* bo   = (const float*)d_in[14];
    float* out = (float*)d_out;

    float* pre;  cudaGetSymbolAddress((void**)&pre,  g_pre);
    float* hall; cudaGetSymbolAddress((void**)&hall, g_h);

    const int REC_SMEM = (8192 + 8192 + 2048 + 8192) * 4;  // 106496 B
    cudaFuncSetAttribute(k_rec, cudaFuncAttributeMaxDynamicSharedMemorySize, REC_SMEM);

    k_pre<<<dim3(512, 12), 256>>>(x, Wzx, Wrx, Whx, pre);
    k_rec<<<128, 256, REC_SMEM>>>(pre, Wzh, Wrh, Whh, bz, br, bh, hall);
    k_out<<<dim3(512, 4), 256>>>(hall, Wo, bo, out);
    (void)in_sizes; (void)n_in; (void)out_size;
}